// round 8
// baseline (speedup 1.0000x reference)
#include <cuda_runtime.h>
#include <cuda_fp16.h>
#include <math.h>
#include <stdint.h>

#define NN 8192
#define FIN 256
#define FOUT 64
#define LRALPHA 0.2f

#define BM 64
#define BK 64
#define NB 80               // B n-rows: 64 out + ones(64) + zeros(65..79)
#define ASTR 72             // A SMEM stride (halves)
#define BSTR 72             // B SMEM stride (halves)
#define NSPLIT 8
#define JCHUNK (NN / NSPLIT)        // 1024
#define NTILES (JCHUNK / BK)        // 16
#define PART_STRIDE 72

// ---- persistent scratch (no allocations allowed) ----
__device__ __align__(16) __half g_Wht[(size_t)NB * NN];   // transposed fp16 Wh + ones/zeros
__device__ __align__(16) float4 g_rowc[NN];  // (f1, exp(f1-m), exp(.2f1-m), 0)
__device__ __align__(16) float4 g_colc[NN];  // (f2, exp(f2),   exp(.2f2),   0)
__device__ float g_f1[NN];
__device__ float g_f2[NN];
__device__ unsigned int g_m2key;
__device__ __align__(16) float g_part[(size_t)NSPLIT * NN * PART_STRIDE];

__device__ __forceinline__ float elu_f(float x) {
    return x > 0.f ? x : expm1f(x);
}
__device__ __forceinline__ unsigned int fkey(float x) {
    unsigned int b = __float_as_uint(x);
    return (b & 0x80000000u) ? ~b : (b | 0x80000000u);
}
__device__ __forceinline__ float fdecode(unsigned int k) {
    return __uint_as_float((k & 0x80000000u) ? (k & 0x7fffffffu) : ~k);
}
__device__ __forceinline__ void cp_async16(uint32_t smem_addr, const void* gptr) {
    asm volatile("cp.async.cg.shared.global [%0], [%1], 16;\n"
                 :: "r"(smem_addr), "l"(gptr));
}
__device__ __forceinline__ void cp_commit() {
    asm volatile("cp.async.commit_group;\n" ::: "memory");
}
__device__ __forceinline__ void cp_wait0() {
    asm volatile("cp.async.wait_group 0;\n" ::: "memory");
}

// ---------------------------------------------------------------------------
// Kernel 1: g_Wht[c][i] = fp16((h @ W)[i][c]); row 64 = 1; rows 65..79 = 0.
// ---------------------------------------------------------------------------
__global__ __launch_bounds__(256) void k_gemm_wh(
    const float* __restrict__ h, const float* __restrict__ W)
{
    __shared__ float hs[16][68];
    __shared__ float wt[64][68];
    __shared__ float ts[64][17];   // transpose staging [c][r_local]

    int t = threadIdx.x;
    int c = t & 63;
    int ry = t >> 6;               // 0..3
    int i0 = blockIdx.x * 16;

    if (blockIdx.x == 0 && t == 0) g_m2key = 0u;  // reset max key each replay

    float acc[4];
#pragma unroll
    for (int r = 0; r < 4; r++) acc[r] = 0.f;

    for (int kt = 0; kt < FIN; kt += 64) {
        __syncthreads();
#pragma unroll
        for (int it = 0; it < 4; it++) {
            int r = ry + 4 * it;
            hs[r][c] = h[(size_t)(i0 + r) * FIN + kt + c];
        }
#pragma unroll
        for (int it = 0; it < 16; it++) {
            int r = ry + 4 * it;
            wt[c][r] = W[(size_t)(kt + r) * FOUT + c];
        }
        __syncthreads();
#pragma unroll
        for (int k4 = 0; k4 < 16; k4++) {
            float4 wv = *(const float4*)&wt[c][k4 * 4];
#pragma unroll
            for (int r = 0; r < 4; r++) {
                float4 hh = *(const float4*)&hs[ry + 4 * r][k4 * 4];
                acc[r] += hh.x * wv.x + hh.y * wv.y + hh.z * wv.z + hh.w * wv.w;
            }
        }
    }
#pragma unroll
    for (int r = 0; r < 4; r++) ts[c][ry + 4 * r] = acc[r];
    __syncthreads();

    // transposed fp16 write
    {
        int c2 = t >> 2, q = t & 3;
        __half2 h0 = __floats2half2_rn(ts[c2][q * 4 + 0], ts[c2][q * 4 + 1]);
        __half2 h1 = __floats2half2_rn(ts[c2][q * 4 + 2], ts[c2][q * 4 + 3]);
        __half2* dst = (__half2*)&g_Wht[(size_t)c2 * NN + i0 + q * 4];
        dst[0] = h0;
        dst[1] = h1;
    }
    // ones / zero rows 64..79 for this i-slice
    {
        int rr = 64 + (t >> 4), ii = t & 15;
        g_Wht[(size_t)rr * NN + i0 + ii] = (rr == 64) ? __float2half(1.0f)
                                                      : __float2half(0.0f);
    }
}

// ---------------------------------------------------------------------------
// Kernel 2: f1/f2 per node + global max of f2.
// ---------------------------------------------------------------------------
__global__ __launch_bounds__(256) void k_fvec(const float* __restrict__ a)
{
    int i = blockIdx.x * 256 + threadIdx.x;
    float s1 = 0.f, s2 = 0.f;
#pragma unroll 8
    for (int c = 0; c < 64; c++) {
        float v = __half2float(g_Wht[(size_t)c * NN + i]);
        s1 += v * __ldg(&a[c]);
        s2 += v * __ldg(&a[64 + c]);
    }
    g_f1[i] = s1;
    g_f2[i] = s2;
    float m = s2;
#pragma unroll
    for (int o = 16; o > 0; o >>= 1)
        m = fmaxf(m, __shfl_xor_sync(0xffffffffu, m, o));
    if ((threadIdx.x & 31) == 0) atomicMax(&g_m2key, fkey(m));
}

// ---------------------------------------------------------------------------
// Kernel 3: row/col exp constants, per-row rescale m_i = lrelu(f1_i + M2).
// ---------------------------------------------------------------------------
__global__ __launch_bounds__(256) void k_consts()
{
    int i = blockIdx.x * 256 + threadIdx.x;
    float M2 = fdecode(g_m2key);
    float f1 = g_f1[i], f2 = g_f2[i];
    float z = f1 + M2;
    float m = (z > 0.f) ? z : LRALPHA * z;
    g_rowc[i] = make_float4(f1, expf(f1 - m), expf(LRALPHA * f1 - m), 0.f);
    g_colc[i] = make_float4(f2, expf(f2), expf(LRALPHA * f2), 0.f);
}

// ---------------------------------------------------------------------------
// Kernel 4: fused masked-softmax attention partials (fp16 m16n8k16 MMA).
// grid = 128 i-blocks x 8 j-splits = 1024 CTAs, 256 thr, 3 CTAs/SM (24 warps).
// BM=64: per-thread regs small enough for 3 co-resident CTAs.
// Per tile (2 syncs, 1 cp-wait):
//   wait0 -> sync1 (B/colc visible + prev MMA drained)
//   wgen -> A (single buffer)   [adj(tt+1) LDG issued right after]
//   issue cp.async B/colc(tt+1) -> buf^1
//   sync2 (A ready) -> MMA(tt)
// Adjacency: direct LDG.64 (__ldcs) -> registers, 8 rows/warp, lane owns
// cols 2l,2l+1; loads fly over sync2 + MMA + sync1.
// SMEM (bytes):
//   [0,      9216)  half  A[64][72]
//   [9216,  32256)  half  B[2][80][72]
//   [32256, 34304)  float4 colcs[2][64]
//   [34304, 35328)  float4 rowcs[64]
// ---------------------------------------------------------------------------
#define SM_A     0
#define SM_B     9216
#define SM_COLC  32256
#define SM_ROWC  34304
#define SMEM_TOTAL 35328

__global__ __launch_bounds__(256, 3) void k_gat(const int* __restrict__ adj)
{
    extern __shared__ __align__(16) char smem[];
    uint32_t sbase = (uint32_t)__cvta_generic_to_shared(smem);

    int t = threadIdx.x;
    int warp = t >> 5, lane = t & 31;
    int i0 = (blockIdx.x >> 3) * BM;
    int split = blockIdx.x & 7;
    int jstart = split * JCHUNK;

    // fixed row constants for the whole CTA
    if (t < BM) ((float4*)(smem + SM_ROWC))[t] = g_rowc[i0 + t];

    // w-gen mapping: warp -> rows 8w..8w+7; lane -> cols 2l, 2l+1
    int wrow0 = warp * 8;
    const int* aptr = adj + (size_t)(i0 + wrow0) * NN + 2 * lane;

    // MMA mapping: 1 m-tile x 5 n-tiles per warp
    int mb = (warp & 3) * 16;
    int nb = (warp >> 2) * 40;
    int g = lane >> 2, tig = lane & 3;

    float acc[5][4];
#pragma unroll
    for (int n = 0; n < 5; n++)
#pragma unroll
        for (int x = 0; x < 4; x++) acc[n][x] = 0.f;

    const uint32_t* As32 = (const uint32_t*)(smem + SM_A);

    // ---- prologue: B(0)+colc(0) cp.async; adj(0) -> registers
    {
#pragma unroll
        for (int it = 0; it < 3; it++) {
            int l = t + 256 * it;
            if (l < 640) {
                int n = l >> 3, kc = l & 7;
                cp_async16(sbase + SM_B + (uint32_t)(n * (BSTR * 2) + kc * 16),
                           &g_Wht[(size_t)n * NN + jstart + kc * 8]);
            }
        }
        if (t < 64)
            cp_async16(sbase + SM_COLC + (uint32_t)t * 16, &g_colc[jstart + t]);
        cp_commit();
    }

    int2 av[8];
#pragma unroll
    for (int r = 0; r < 8; r++)
        av[r] = __ldcs((const int2*)(aptr + (size_t)r * NN + jstart));

    for (int tt = 0; tt < NTILES; tt++) {
        int buf = tt & 1;
        int j0 = jstart + tt * BK;

        // 1. B(tt)/colc(tt) complete (single outstanding group), then
        //    barrier: cross-thread visibility + all warps drained MMA(tt-1)
        cp_wait0();
        __syncthreads();

        // 2. w-gen: registers(adj) + smem consts -> fp16 A[64][64]
        {
            const float4* cl = (const float4*)(smem + SM_COLC + buf * 1024);
            float4 cc0 = cl[2 * lane];
            float4 cc1 = cl[2 * lane + 1];
            const float4* rw = (const float4*)(smem + SM_ROWC) + wrow0;
            __half2* adst = (__half2*)(smem + SM_A) + lane;
#pragma unroll
            for (int r = 0; r < 8; r++) {
                float4 rc = rw[r];                 // LDS broadcast
                int2 a2 = av[r];
                float w0 = ((rc.x + cc0.x) > 0.f) ? rc.y * cc0.y : rc.z * cc0.z;
                float w1 = ((rc.x + cc1.x) > 0.f) ? rc.y * cc1.y : rc.z * cc1.z;
                w0 = a2.x ? w0 : 0.f;
                w1 = a2.y ? w1 : 0.f;
                adst[(wrow0 + r) * (ASTR / 2)] = __floats2half2_rn(w0, w1);
            }
        }

        // 3. stream adj(tt+1) into registers (flies over sync + MMA)
        if (tt + 1 < NTILES) {
            int jn = j0 + BK;
#pragma unroll
            for (int r = 0; r < 8; r++)
                av[r] = __ldcs((const int2*)(aptr + (size_t)r * NN + jn));
        }

        // 4. issue B(tt+1)/colc(tt+1) into buf^1 (prev MMA drained at sync1)
        if (tt + 1 < NTILES) {
            int jn = j0 + BK;
            uint32_t bd = sbase + SM_B + (uint32_t)(buf ^ 1) * (NB * BSTR * 2);
            uint32_t cd = sbase + SM_COLC + (uint32_t)(buf ^ 1) * 1024;
#pragma unroll
            for (int it = 0; it < 3; it++) {
                int l = t + 256 * it;
                if (l < 640) {
                    int n = l >> 3, kc = l & 7;
                    cp_async16(bd + (uint32_t)(n * (BSTR * 2) + kc * 16),
                               &g_Wht[(size_t)n * NN + jn + kc * 8]);
                }
            }
            if (t < 64) cp_async16(cd + (uint32_t)t * 16, &g_colc[jn + t]);
            cp_commit();
        }

        // 5. A visible
        __syncthreads();

        // 6. MMA: 4 k-steps x 5 n-tiles
        const uint32_t* Bs32 = (const uint32_t*)(smem + SM_B + buf * (NB * BSTR * 2));
#pragma unroll
        for (int kt = 0; kt < 4; kt++) {
            int kb = kt * 16 + 2 * tig;          // half index (even)
            uint32_t a0[4];
            {
                int r0 = mb + g;
                a0[0] = As32[r0 * (ASTR / 2) + (kb >> 1)];
                a0[1] = As32[(r0 + 8) * (ASTR / 2) + (kb >> 1)];
                a0[2] = As32[r0 * (ASTR / 2) + ((kb + 8) >> 1)];
                a0[3] = As32[(r0 + 8) * (ASTR / 2) + ((kb + 8) >> 1)];
            }
#pragma unroll
            for (int nt = 0; nt < 5; nt++) {
                int n = nb + nt * 8 + g;
                uint32_t b0 = Bs32[n * (BSTR / 2) + (kb >> 1)];
                uint32_t b1 = Bs32[n * (BSTR / 2) + ((kb + 8) >> 1)];
                asm volatile(
                    "mma.sync.aligned.m16n8k16.row.col.f32.f16.f16.f32 "
                    "{%0,%1,%2,%3}, {%4,%5,%6,%7}, {%8,%9}, {%0,%1,%2,%3};\n"
                    : "+f"(acc[nt][0]), "+f"(acc[nt][1]),
                      "+f"(acc[nt][2]), "+f"(acc[nt][3])
                    : "r"(a0[0]), "r"(a0[1]), "r"(a0[2]), "r"(a0[3]),
                      "r"(b0), "r"(b1));
            }
        }
    }

    // ---- write partials: nums (cols 0..63) + den (logical col 64)
    float* pp = &g_part[((size_t)split * NN + i0) * PART_STRIDE];
    {
        int r0 = mb + g, r1 = r0 + 8;
#pragma unroll
        for (int nt = 0; nt < 5; nt++) {
            int nb2 = nb + nt * 8 + 2 * tig;
            if (nb2 < 64) {
                pp[(size_t)r0 * PART_STRIDE + nb2] = acc[nt][0];
                pp[(size_t)r1 * PART_STRIDE + nb2] = acc[nt][2];
            }
            if (nb2 + 1 < 64) {
                pp[(size_t)r0 * PART_STRIDE + nb2 + 1] = acc[nt][1];
                pp[(size_t)r1 * PART_STRIDE + nb2 + 1] = acc[nt][3];
            }
        }
        if (nb == 40 && tig == 0) {    // col 64 = 40 + 3*8 + 0
            pp[(size_t)r0 * PART_STRIDE + 64] = acc[3][0];
            pp[(size_t)r1 * PART_STRIDE + 64] = acc[3][2];
        }
    }
}

// ---------------------------------------------------------------------------
// Kernel 5: reduce partials across splits + elu (float4 per thread).
// ---------------------------------------------------------------------------
__global__ __launch_bounds__(256) void k_reduce(float* __restrict__ out)
{
    int idx = blockIdx.x * 256 + threadIdx.x;   // 0 .. NN*16
    int i = idx >> 4;
    int c4 = (idx & 15) * 4;

    float4 num = make_float4(0.f, 0.f, 0.f, 0.f);
    float den = 0.f;
#pragma unroll
    for (int s = 0; s < NSPLIT; s++) {
        const float* pp = &g_part[((size_t)s * NN + i) * PART_STRIDE];
        float4 v = *(const float4*)(pp + c4);
        num.x += v.x; num.y += v.y; num.z += v.z; num.w += v.w;
        den += pp[64];
    }
    float4 r;
    r.x = elu_f(num.x / den);
    r.y = elu_f(num.y / den);
    r.z = elu_f(num.z / den);
    r.w = elu_f(num.w / den);
    *(float4*)&out[(size_t)i * FOUT + c4] = r;
}

// ---------------------------------------------------------------------------
extern "C" void kernel_launch(void* const* d_in, const int* in_sizes, int n_in,
                              void* d_out, int out_size)
{
    const float* h   = (const float*)d_in[0];
    const int*   adj = (const int*)d_in[1];
    const float* W   = (const float*)d_in[2];
    const float* a   = (const float*)d_in[3];
    float* out = (float*)d_out;

    k_gemm_wh<<<NN / 16, 256>>>(h, W);
    k_fvec<<<NN / 256, 256>>>(a);
    k_consts<<<NN / 256, 256>>>();
    k_gat<<<(NN / BM) * NSPLIT, 256, SMEM_TOTAL>>>(adj);
    k_reduce<<<NN * 16 / 256, 256>>>(out);
}

// round 9
// speedup vs baseline: 1.0296x; 1.0296x over previous
#include <cuda_runtime.h>
#include <cuda_fp16.h>
#include <math.h>
#include <stdint.h>

#define NN 8192
#define FIN 256
#define FOUT 64
#define LRALPHA 0.2f

#define BM 128
#define BK 64
#define NB 80               // B n-rows: 64 out + ones(64) + zeros(65..79)
#define ASTR 72             // A SMEM stride (halves)
#define BSTR 72             // B SMEM stride (halves)
#define NSPLIT 4
#define JCHUNK (NN / NSPLIT)        // 2048
#define NTILES (JCHUNK / BK)        // 32
#define PART_STRIDE 72

// ---- persistent scratch (no allocations allowed) ----
__device__ __align__(16) __half g_Wht[(size_t)NB * NN];   // transposed fp16 Wh + ones/zeros
__device__ __align__(16) float4 g_rowc[NN];  // (f1, exp(f1-m), exp(.2f1-m), 0)
__device__ __align__(16) float4 g_colc[NN];  // (f2, exp(f2),   exp(.2f2),   0)
__device__ float g_f1[NN];
__device__ float g_f2[NN];
__device__ unsigned int g_m2key;
__device__ __align__(16) float g_part[(size_t)NSPLIT * NN * PART_STRIDE];

__device__ __forceinline__ float elu_f(float x) {
    return x > 0.f ? x : expm1f(x);
}
__device__ __forceinline__ unsigned int fkey(float x) {
    unsigned int b = __float_as_uint(x);
    return (b & 0x80000000u) ? ~b : (b | 0x80000000u);
}
__device__ __forceinline__ float fdecode(unsigned int k) {
    return __uint_as_float((k & 0x80000000u) ? (k & 0x7fffffffu) : ~k);
}
__device__ __forceinline__ void cp_async16(uint32_t smem_addr, const void* gptr) {
    asm volatile("cp.async.cg.shared.global [%0], [%1], 16;\n"
                 :: "r"(smem_addr), "l"(gptr));
}
__device__ __forceinline__ void cp_commit() {
    asm volatile("cp.async.commit_group;\n" ::: "memory");
}
__device__ __forceinline__ void cp_wait0() {
    asm volatile("cp.async.wait_group 0;\n" ::: "memory");
}
__device__ __forceinline__ void ldsm_x4(uint32_t& r0, uint32_t& r1,
                                        uint32_t& r2, uint32_t& r3, uint32_t a) {
    asm volatile("ldmatrix.sync.aligned.m8n8.x4.shared.b16 {%0,%1,%2,%3}, [%4];"
                 : "=r"(r0), "=r"(r1), "=r"(r2), "=r"(r3) : "r"(a));
}
__device__ __forceinline__ void ldsm_x2(uint32_t& r0, uint32_t& r1, uint32_t a) {
    asm volatile("ldmatrix.sync.aligned.m8n8.x2.shared.b16 {%0,%1}, [%2];"
                 : "=r"(r0), "=r"(r1) : "r"(a));
}

// ---------------------------------------------------------------------------
// Kernel 1: g_Wht[c][i] = fp16((h @ W)[i][c]); row 64 = 1; rows 65..79 = 0.
// ---------------------------------------------------------------------------
__global__ __launch_bounds__(256) void k_gemm_wh(
    const float* __restrict__ h, const float* __restrict__ W)
{
    __shared__ float hs[16][68];
    __shared__ float wt[64][68];
    __shared__ float ts[64][17];   // transpose staging [c][r_local]

    int t = threadIdx.x;
    int c = t & 63;
    int ry = t >> 6;               // 0..3
    int i0 = blockIdx.x * 16;

    if (blockIdx.x == 0 && t == 0) g_m2key = 0u;  // reset max key each replay

    float acc[4];
#pragma unroll
    for (int r = 0; r < 4; r++) acc[r] = 0.f;

    for (int kt = 0; kt < FIN; kt += 64) {
        __syncthreads();
#pragma unroll
        for (int it = 0; it < 4; it++) {
            int r = ry + 4 * it;
            hs[r][c] = h[(size_t)(i0 + r) * FIN + kt + c];
        }
#pragma unroll
        for (int it = 0; it < 16; it++) {
            int r = ry + 4 * it;
            wt[c][r] = W[(size_t)(kt + r) * FOUT + c];
        }
        __syncthreads();
#pragma unroll
        for (int k4 = 0; k4 < 16; k4++) {
            float4 wv = *(const float4*)&wt[c][k4 * 4];
#pragma unroll
            for (int r = 0; r < 4; r++) {
                float4 hh = *(const float4*)&hs[ry + 4 * r][k4 * 4];
                acc[r] += hh.x * wv.x + hh.y * wv.y + hh.z * wv.z + hh.w * wv.w;
            }
        }
    }
#pragma unroll
    for (int r = 0; r < 4; r++) ts[c][ry + 4 * r] = acc[r];
    __syncthreads();

    // transposed fp16 write
    {
        int c2 = t >> 2, q = t & 3;
        __half2 h0 = __floats2half2_rn(ts[c2][q * 4 + 0], ts[c2][q * 4 + 1]);
        __half2 h1 = __floats2half2_rn(ts[c2][q * 4 + 2], ts[c2][q * 4 + 3]);
        __half2* dst = (__half2*)&g_Wht[(size_t)c2 * NN + i0 + q * 4];
        dst[0] = h0;
        dst[1] = h1;
    }
    // ones / zero rows 64..79 for this i-slice
    {
        int rr = 64 + (t >> 4), ii = t & 15;
        g_Wht[(size_t)rr * NN + i0 + ii] = (rr == 64) ? __float2half(1.0f)
                                                      : __float2half(0.0f);
    }
}

// ---------------------------------------------------------------------------
// Kernel 2: f1/f2 per node + global max of f2.
// ---------------------------------------------------------------------------
__global__ __launch_bounds__(256) void k_fvec(const float* __restrict__ a)
{
    int i = blockIdx.x * 256 + threadIdx.x;
    float s1 = 0.f, s2 = 0.f;
#pragma unroll 8
    for (int c = 0; c < 64; c++) {
        float v = __half2float(g_Wht[(size_t)c * NN + i]);
        s1 += v * __ldg(&a[c]);
        s2 += v * __ldg(&a[64 + c]);
    }
    g_f1[i] = s1;
    g_f2[i] = s2;
    float m = s2;
#pragma unroll
    for (int o = 16; o > 0; o >>= 1)
        m = fmaxf(m, __shfl_xor_sync(0xffffffffu, m, o));
    if ((threadIdx.x & 31) == 0) atomicMax(&g_m2key, fkey(m));
}

// ---------------------------------------------------------------------------
// Kernel 3: row/col exp constants, per-row rescale m_i = lrelu(f1_i + M2).
// ---------------------------------------------------------------------------
__global__ __launch_bounds__(256) void k_consts()
{
    int i = blockIdx.x * 256 + threadIdx.x;
    float M2 = fdecode(g_m2key);
    float f1 = g_f1[i], f2 = g_f2[i];
    float z = f1 + M2;
    float m = (z > 0.f) ? z : LRALPHA * z;
    g_rowc[i] = make_float4(f1, expf(f1 - m), expf(LRALPHA * f1 - m), 0.f);
    g_colc[i] = make_float4(f2, expf(f2), expf(LRALPHA * f2), 0.f);
}

// ---------------------------------------------------------------------------
// Kernel 4: fused masked-softmax attention partials (fp16 m16n8k16 MMA,
// ldmatrix fragment loads).  grid = 64 i-blocks x 4 j-splits = 256 CTAs,
// 256 thr, 2 CTAs/SM.
// Per tile (2 syncs, 1 cp-wait):
//   cp_wait0 -> sync1 (B/colc(tt) visible + MMA(tt-1) drained everywhere)
//   wgen -> A (single buffer); adj(tt+1) LDG.64 stream -> registers
//   issue cp.async B/colc(tt+1) -> buf^1; sync2 (A visible) -> MMA(tt)
// Fragments: A via 2x ldmatrix.x4 per k-step; B via 2x ldmatrix.x4 + x2.
// SMEM (bytes):
//   [0,     18432)  half  A[128][72]
//   [18432, 41472)  half  B[2][80][72]
//   [41472, 43520)  float4 colcs[2][64]
//   [43520, 45568)  float4 rowcs[128]
// ---------------------------------------------------------------------------
#define SM_A     0
#define SM_B     18432
#define SM_COLC  41472
#define SM_ROWC  43520
#define SMEM_TOTAL 45568

__global__ __launch_bounds__(256, 2) void k_gat(const int* __restrict__ adj)
{
    extern __shared__ __align__(16) char smem[];
    uint32_t sbase = (uint32_t)__cvta_generic_to_shared(smem);

    int t = threadIdx.x;
    int warp = t >> 5, lane = t & 31;
    int i0 = (blockIdx.x >> 2) * BM;
    int split = blockIdx.x & 3;
    int jstart = split * JCHUNK;

    // fixed row constants for the whole CTA
    if (t < 128) ((float4*)(smem + SM_ROWC))[t] = g_rowc[i0 + t];

    // w-gen mapping: warp -> rows 16w..16w+15; lane -> cols 2l, 2l+1
    int wrow0 = warp * 16;
    const int* aptr = adj + (size_t)(i0 + wrow0) * NN + 2 * lane;

    // MMA mapping
    int mb = (warp & 3) * 32;      // 32 rows (2 m-tiles)
    int nb = (warp >> 2) * 40;     // 40 cols (5 n-tiles)
    int g = lane >> 2, tig = lane & 3;

    // ldmatrix lane addresses (byte offsets in halves*2)
    // A x4: lane l -> row mb + (l&15) (+16 for 2nd m-tile), col (l>>4)*8
    uint32_t a_ad0 = sbase + SM_A +
        (uint32_t)(((mb + (lane & 15)) * ASTR + ((lane >> 4) << 3)) * 2);
    uint32_t a_ad1 = a_ad0 + 16 * ASTR * 2;
    // B x4 (nt pair p): lane l -> row nb + p*16 + (l>>4)*8 + (l&7), col ((l>>3)&1)*8
    uint32_t b_off_p = (uint32_t)(((nb + ((lane >> 4) << 3) + (lane & 7)) * BSTR
                                   + (((lane >> 3) & 1) << 3)) * 2);
    // B x2 (nt=4): lanes 0-15 -> row nb+32+(l&7), col ((l>>3)&1)*8
    uint32_t b_off_2 = (uint32_t)(((nb + 32 + (lane & 7)) * BSTR
                                   + (((lane >> 3) & 1) << 3)) * 2);

    float acc[2][5][4];
#pragma unroll
    for (int m = 0; m < 2; m++)
#pragma unroll
        for (int n = 0; n < 5; n++)
#pragma unroll
            for (int x = 0; x < 4; x++) acc[m][n][x] = 0.f;

    // ---- prologue: B(0)+colc(0) cp.async into buf 0; adj(0) -> registers
    {
#pragma unroll
        for (int it = 0; it < 3; it++) {
            int l = t + 256 * it;
            if (l < 640) {
                int n = l >> 3, kc = l & 7;
                cp_async16(sbase + SM_B + (uint32_t)(n * (BSTR * 2) + kc * 16),
                           &g_Wht[(size_t)n * NN + jstart + kc * 8]);
            }
        }
        if (t < 64)
            cp_async16(sbase + SM_COLC + (uint32_t)t * 16, &g_colc[jstart + t]);
        cp_commit();
    }

    int2 av[16];
#pragma unroll
    for (int r = 0; r < 16; r++)
        av[r] = __ldcs((const int2*)(aptr + (size_t)r * NN + jstart));

    for (int tt = 0; tt < NTILES; tt++) {
        int buf = tt & 1;
        int j0 = jstart + tt * BK;

        // 1. B(tt)/colc(tt) complete; barrier doubles as MMA(tt-1) drain
        cp_wait0();
        __syncthreads();

        // 2. w-gen: registers(adj) + smem consts -> fp16 A[128][64]
        {
            const float4* cl = (const float4*)(smem + SM_COLC + buf * 1024);
            float4 cc0 = cl[2 * lane];
            float4 cc1 = cl[2 * lane + 1];
            const float4* rw = (const float4*)(smem + SM_ROWC) + wrow0;
            __half2* adst = (__half2*)(smem + SM_A) + lane;
#pragma unroll
            for (int r = 0; r < 16; r++) {
                float4 rc = rw[r];                 // LDS broadcast
                int2 a2 = av[r];
                float w0 = ((rc.x + cc0.x) > 0.f) ? rc.y * cc0.y : rc.z * cc0.z;
                float w1 = ((rc.x + cc1.x) > 0.f) ? rc.y * cc1.y : rc.z * cc1.z;
                w0 = a2.x ? w0 : 0.f;
                w1 = a2.y ? w1 : 0.f;
                adst[(wrow0 + r) * (ASTR / 2)] = __floats2half2_rn(w0, w1);
            }
        }

        // 3. stream adj(tt+1) into registers (flies over sync + MMA)
        if (tt + 1 < NTILES) {
            int jn = j0 + BK;
#pragma unroll
            for (int r = 0; r < 16; r++)
                av[r] = __ldcs((const int2*)(aptr + (size_t)r * NN + jn));
        }

        // 4. issue B(tt+1)/colc(tt+1) into buf^1 (MMA(tt-1) drained at sync1)
        if (tt + 1 < NTILES) {
            int jn = j0 + BK;
            uint32_t bd = sbase + SM_B + (uint32_t)(buf ^ 1) * (NB * BSTR * 2);
            uint32_t cd = sbase + SM_COLC + (uint32_t)(buf ^ 1) * 1024;
#pragma unroll
            for (int it = 0; it < 3; it++) {
                int l = t + 256 * it;
                if (l < 640) {
                    int n = l >> 3, kc = l & 7;
                    cp_async16(bd + (uint32_t)(n * (BSTR * 2) + kc * 16),
                               &g_Wht[(size_t)n * NN + jn + kc * 8]);
                }
            }
            if (t < 64) cp_async16(cd + (uint32_t)t * 16, &g_colc[jn + t]);
            cp_commit();
        }

        // 5. A visible
        __syncthreads();

        // 6. MMA: 4 k-steps x (2 m-tiles x 5 n-tiles), ldmatrix fragments
        uint32_t b_base = sbase + SM_B + (uint32_t)buf * (NB * BSTR * 2);
#pragma unroll
        for (int kt = 0; kt < 4; kt++) {
            uint32_t koff = (uint32_t)kt * 32;    // 16 halves
            uint32_t a0[4], a1[4], bb[10];
            ldsm_x4(a0[0], a0[1], a0[2], a0[3], a_ad0 + koff);
            ldsm_x4(a1[0], a1[1], a1[2], a1[3], a_ad1 + koff);
            ldsm_x4(bb[0], bb[1], bb[2], bb[3], b_base + b_off_p + koff);
            ldsm_x4(bb[4], bb[5], bb[6], bb[7],
                    b_base + b_off_p + 16 * BSTR * 2 + koff);
            ldsm_x2(bb[8], bb[9], b_base + b_off_2 + koff);
#pragma unroll
            for (int nt = 0; nt < 5; nt++) {
                uint32_t b0 = bb[2 * nt], b1 = bb[2 * nt + 1];
                asm volatile(
                    "mma.sync.aligned.m16n8k16.row.col.f32.f16.f16.f32 "
                    "{%0,%1,%2,%3}, {%4,%5,%6,%7}, {%8,%9}, {%0,%1,%2,%3};\n"
                    : "+f"(acc[0][nt][0]), "+f"(acc[0][nt][1]),
                      "+f"(acc[0][nt][2]), "+f"(acc[0][nt][3])
                    : "r"(a0[0]), "r"(a0[1]), "r"(a0[2]), "r"(a0[3]),
                      "r"(b0), "r"(b1));
                asm volatile(
                    "mma.sync.aligned.m16n8k16.row.col.f32.f16.f16.f32 "
                    "{%0,%1,%2,%3}, {%4,%5,%6,%7}, {%8,%9}, {%0,%1,%2,%3};\n"
                    : "+f"(acc[1][nt][0]), "+f"(acc[1][nt][1]),
                      "+f"(acc[1][nt][2]), "+f"(acc[1][nt][3])
                    : "r"(a1[0]), "r"(a1[1]), "r"(a1[2]), "r"(a1[3]),
                      "r"(b0), "r"(b1));
            }
        }
    }

    // ---- write partials: nums (cols 0..63) + den (logical col 64)
    float* pp = &g_part[((size_t)split * NN + i0) * PART_STRIDE];
#pragma unroll
    for (int m = 0; m < 2; m++) {
        int r0 = mb + m * 16 + g, r1 = r0 + 8;
#pragma unroll
        for (int nt = 0; nt < 5; nt++) {
            int nb2 = nb + nt * 8 + 2 * tig;
            if (nb2 < 64) {
                pp[(size_t)r0 * PART_STRIDE + nb2] = acc[m][nt][0];
                pp[(size_t)r1 * PART_STRIDE + nb2] = acc[m][nt][2];
            }
            if (nb2 + 1 < 64) {
                pp[(size_t)r0 * PART_STRIDE + nb2 + 1] = acc[m][nt][1];
                pp[(size_t)r1 * PART_STRIDE + nb2 + 1] = acc[m][nt][3];
            }
        }
        if (nb == 40 && tig == 0) {    // col 64 = 40 + 3*8 + 0
            pp[(size_t)r0 * PART_STRIDE + 64] = acc[m][3][0];
            pp[(size_t)r1 * PART_STRIDE + 64] = acc[m][3][2];
        }
    }
}

// ---------------------------------------------------------------------------
// Kernel 5: reduce partials across splits + elu (float4 per thread).
// ---------------------------------------------------------------------------
__global__ __launch_bounds__(256) void k_reduce(float* __restrict__ out)
{
    int idx = blockIdx.x * 256 + threadIdx.x;   // 0 .. NN*16
    int i = idx >> 4;
    int c4 = (idx & 15) * 4;

    float4 num = make_float4(0.f, 0.f, 0.f, 0.f);
    float den = 0.f;
#pragma unroll
    for (int s = 0; s < NSPLIT; s++) {
        const float* pp = &g_part[((size_t)s * NN + i) * PART_STRIDE];
        float4 v = *(const float4*)(pp + c4);
        num.x += v.x; num.y += v.y; num.z += v.z; num.w += v.w;
        den += pp[64];
    }
    float4 r;
    r.x = elu_f(num.x / den);
    r.y = elu_f(num.y / den);
    r.z = elu_f(num.z / den);
    r.w = elu_f(num.w / den);
    *(float4*)&out[(size_t)i * FOUT + c4] = r;
}

// ---------------------------------------------------------------------------
extern "C" void kernel_launch(void* const* d_in, const int* in_sizes, int n_in,
                              void* d_out, int out_size)
{
    const float* h   = (const float*)d_in[0];
    const int*   adj = (const int*)d_in[1];
    const float* W   = (const float*)d_in[2];
    const float* a   = (const float*)d_in[3];
    float* out = (float*)d_out;

    cudaFuncSetAttribute(k_gat, cudaFuncAttributeMaxDynamicSharedMemorySize,
                         SMEM_TOTAL);

    k_gemm_wh<<<NN / 16, 256>>>(h, W);
    k_fvec<<<NN / 256, 256>>>(a);
    k_consts<<<NN / 256, 256>>>();
    k_gat<<<(NN / BM) * NSPLIT, 256, SMEM_TOTAL>>>(adj);
    k_reduce<<<NN * 16 / 256, 256>>>(out);
}

// round 10
// speedup vs baseline: 1.2832x; 1.2463x over previous
#include <cuda_runtime.h>
#include <cuda_fp16.h>
#include <math.h>
#include <stdint.h>

#define NN 8192
#define FIN 256
#define FOUT 64
#define LRALPHA 0.2f

#define BM 128
#define BK 64
#define NB 80               // B n-rows: 64 out + ones(64) + zeros(65..79)
#define ASTR 72             // A SMEM stride (halves)
#define BSTR 72             // B SMEM stride (halves)
#define NSPLIT 4
#define JCHUNK (NN / NSPLIT)        // 2048
#define NTILES (JCHUNK / BK)        // 32
#define PART_STRIDE 72

// ---- persistent scratch (no allocations allowed) ----
__device__ __align__(16) __half g_Wht[(size_t)NB * NN];   // transposed fp16 Wh + ones/zeros
__device__ __align__(16) float4 g_rowc[NN];  // (f1, exp(f1-m), exp(.2f1-m), 0)
__device__ __align__(16) float4 g_colc[NN];  // (f2, exp(f2),   exp(.2f2),   0)
__device__ float g_f1[NN];
__device__ float g_f2[NN];
__device__ unsigned int g_m2key;
__device__ __align__(16) float g_part[(size_t)NSPLIT * NN * PART_STRIDE];

__device__ __forceinline__ float elu_f(float x) {
    return x > 0.f ? x : expm1f(x);
}
__device__ __forceinline__ unsigned int fkey(float x) {
    unsigned int b = __float_as_uint(x);
    return (b & 0x80000000u) ? ~b : (b | 0x80000000u);
}
__device__ __forceinline__ float fdecode(unsigned int k) {
    return __uint_as_float((k & 0x80000000u) ? (k & 0x7fffffffu) : ~k);
}
__device__ __forceinline__ void cp_async16(uint32_t smem_addr, const void* gptr) {
    asm volatile("cp.async.cg.shared.global [%0], [%1], 16;\n"
                 :: "r"(smem_addr), "l"(gptr));
}
__device__ __forceinline__ void cp_commit() {
    asm volatile("cp.async.commit_group;\n" ::: "memory");
}
__device__ __forceinline__ void cp_wait1() {
    asm volatile("cp.async.wait_group 1;\n" ::: "memory");
}
__device__ __forceinline__ void cp_wait0() {
    asm volatile("cp.async.wait_group 0;\n" ::: "memory");
}
__device__ __forceinline__ void ldsm_x4(uint32_t& r0, uint32_t& r1,
                                        uint32_t& r2, uint32_t& r3, uint32_t a) {
    asm volatile("ldmatrix.sync.aligned.m8n8.x4.shared.b16 {%0,%1,%2,%3}, [%4];"
                 : "=r"(r0), "=r"(r1), "=r"(r2), "=r"(r3) : "r"(a));
}
__device__ __forceinline__ void ldsm_x2(uint32_t& r0, uint32_t& r1, uint32_t a) {
    asm volatile("ldmatrix.sync.aligned.m8n8.x2.shared.b16 {%0,%1}, [%2];"
                 : "=r"(r0), "=r"(r1) : "r"(a));
}

// ---------------------------------------------------------------------------
// Kernel 1: g_Wht[c][i] = fp16((h @ W)[i][c]); row 64 = 1; rows 65..79 = 0.
// Conflict-free layout: wt2[k][c] (consecutive-c float4 loads), hs broadcast.
// Thread = (row rr = t>>4, col-group cg = t&15); acc = float4 (4 cols).
// ---------------------------------------------------------------------------
__global__ __launch_bounds__(256) void k_gemm_wh(
    const float* __restrict__ h, const float* __restrict__ W)
{
    __shared__ float hs[16][68];
    __shared__ float wt2[64][68];
    __shared__ float ts[64][17];   // transpose staging [c][r_local]

    int t = threadIdx.x;
    int c = t & 63;
    int ry = t >> 6;               // 0..3 (staging)
    int i0 = blockIdx.x * 16;

    int rr = t >> 4;               // 0..15 (compute row)
    int cg = t & 15;               // 0..15 (compute col-group)

    if (blockIdx.x == 0 && t == 0) g_m2key = 0u;  // reset max key each replay

    float4 acc = make_float4(0.f, 0.f, 0.f, 0.f);

    for (int kt = 0; kt < FIN; kt += 64) {
        __syncthreads();
#pragma unroll
        for (int it = 0; it < 4; it++) {
            int r = ry + 4 * it;
            hs[r][c] = h[(size_t)(i0 + r) * FIN + kt + c];
        }
#pragma unroll
        for (int it = 0; it < 16; it++) {
            int r = ry + 4 * it;
            wt2[r][c] = W[(size_t)(kt + r) * FOUT + c];
        }
        __syncthreads();
#pragma unroll
        for (int k4 = 0; k4 < 16; k4++) {
            float4 hv = *(const float4*)&hs[rr][k4 * 4];   // broadcast
            float4 w0 = *(const float4*)&wt2[k4 * 4 + 0][cg * 4];
            float4 w1 = *(const float4*)&wt2[k4 * 4 + 1][cg * 4];
            float4 w2 = *(const float4*)&wt2[k4 * 4 + 2][cg * 4];
            float4 w3 = *(const float4*)&wt2[k4 * 4 + 3][cg * 4];
            acc.x += hv.x * w0.x + hv.y * w1.x + hv.z * w2.x + hv.w * w3.x;
            acc.y += hv.x * w0.y + hv.y * w1.y + hv.z * w2.y + hv.w * w3.y;
            acc.z += hv.x * w0.z + hv.y * w1.z + hv.z * w2.z + hv.w * w3.z;
            acc.w += hv.x * w0.w + hv.y * w1.w + hv.z * w2.w + hv.w * w3.w;
        }
    }
    // stage for transpose: ts[col][row]
    ts[cg * 4 + 0][rr] = acc.x;
    ts[cg * 4 + 1][rr] = acc.y;
    ts[cg * 4 + 2][rr] = acc.z;
    ts[cg * 4 + 3][rr] = acc.w;
    __syncthreads();

    // transposed fp16 write
    {
        int c2 = t >> 2, q = t & 3;
        __half2 h0 = __floats2half2_rn(ts[c2][q * 4 + 0], ts[c2][q * 4 + 1]);
        __half2 h1 = __floats2half2_rn(ts[c2][q * 4 + 2], ts[c2][q * 4 + 3]);
        __half2* dst = (__half2*)&g_Wht[(size_t)c2 * NN + i0 + q * 4];
        dst[0] = h0;
        dst[1] = h1;
    }
    // ones / zero rows 64..79 for this i-slice
    {
        int rz = 64 + (t >> 4), ii = t & 15;
        g_Wht[(size_t)rz * NN + i0 + ii] = (rz == 64) ? __float2half(1.0f)
                                                      : __float2half(0.0f);
    }
}

// ---------------------------------------------------------------------------
// Kernel 2: f1/f2 per node + global max of f2.
// ---------------------------------------------------------------------------
__global__ __launch_bounds__(256) void k_fvec(const float* __restrict__ a)
{
    int i = blockIdx.x * 256 + threadIdx.x;
    float s1 = 0.f, s2 = 0.f;
#pragma unroll 8
    for (int c = 0; c < 64; c++) {
        float v = __half2float(g_Wht[(size_t)c * NN + i]);
        s1 += v * __ldg(&a[c]);
        s2 += v * __ldg(&a[64 + c]);
    }
    g_f1[i] = s1;
    g_f2[i] = s2;
    float m = s2;
#pragma unroll
    for (int o = 16; o > 0; o >>= 1)
        m = fmaxf(m, __shfl_xor_sync(0xffffffffu, m, o));
    if ((threadIdx.x & 31) == 0) atomicMax(&g_m2key, fkey(m));
}

// ---------------------------------------------------------------------------
// Kernel 3: row/col exp constants, per-row rescale m_i = lrelu(f1_i + M2).
// ---------------------------------------------------------------------------
__global__ __launch_bounds__(256) void k_consts()
{
    int i = blockIdx.x * 256 + threadIdx.x;
    float M2 = fdecode(g_m2key);
    float f1 = g_f1[i], f2 = g_f2[i];
    float z = f1 + M2;
    float m = (z > 0.f) ? z : LRALPHA * z;
    g_rowc[i] = make_float4(f1, expf(f1 - m), expf(LRALPHA * f1 - m), 0.f);
    g_colc[i] = make_float4(f2, expf(f2), expf(LRALPHA * f2), 0.f);
}

// ---------------------------------------------------------------------------
// Kernel 4: fused masked-softmax attention partials (fp16 m16n8k16 MMA,
// ldmatrix fragments, R6 pipeline schedule).
// grid = 64 i-blocks x 4 j-splits = 256 CTAs, 256 thr, 2 CTAs/SM.
// Per tile (R6 schedule — the proven one):
//   sync1 (MMA(tt-1) drained) -> issue B(tt+1)/colc(tt+1) into buf^1
//   cp_wait1 (group(tt) complete, issued a FULL TILE earlier -> never blocks;
//             group(tt+1) stays in flight)
//   sync2 (visibility) -> wgen A from adj regs -> adj(tt+1) LDG stream
//   sync3 (A visible) -> MMA(tt)
// SMEM (bytes):
//   [0,     18432)  half  A[128][72]
//   [18432, 41472)  half  B[2][80][72]
//   [41472, 43520)  float4 colcs[2][64]
//   [43520, 45568)  float4 rowcs[128]
// ---------------------------------------------------------------------------
#define SM_A     0
#define SM_B     18432
#define SM_COLC  41472
#define SM_ROWC  43520
#define SMEM_TOTAL 45568

__global__ __launch_bounds__(256, 2) void k_gat(const int* __restrict__ adj)
{
    extern __shared__ __align__(16) char smem[];
    uint32_t sbase = (uint32_t)__cvta_generic_to_shared(smem);

    int t = threadIdx.x;
    int warp = t >> 5, lane = t & 31;
    int i0 = (blockIdx.x >> 2) * BM;
    int split = blockIdx.x & 3;
    int jstart = split * JCHUNK;

    // fixed row constants for the whole CTA
    if (t < 128) ((float4*)(smem + SM_ROWC))[t] = g_rowc[i0 + t];

    // w-gen mapping: warp -> rows 16w..16w+15; lane -> cols 2l, 2l+1
    int wrow0 = warp * 16;
    const int* aptr = adj + (size_t)(i0 + wrow0) * NN + 2 * lane;

    // MMA mapping
    int mb = (warp & 3) * 32;      // 32 rows (2 m-tiles)
    int nb = (warp >> 2) * 40;     // 40 cols (5 n-tiles)
    int g = lane >> 2, tig = lane & 3;

    // ldmatrix lane addresses
    uint32_t a_ad0 = sbase + SM_A +
        (uint32_t)(((mb + (lane & 15)) * ASTR + ((lane >> 4) << 3)) * 2);
    uint32_t a_ad1 = a_ad0 + 16 * ASTR * 2;
    uint32_t b_off_p = (uint32_t)(((nb + ((lane >> 4) << 3) + (lane & 7)) * BSTR
                                   + (((lane >> 3) & 1) << 3)) * 2);
    uint32_t b_off_2 = (uint32_t)(((nb + 32 + (lane & 7)) * BSTR
                                   + (((lane >> 3) & 1) << 3)) * 2);

    float acc[2][5][4];
#pragma unroll
    for (int m = 0; m < 2; m++)
#pragma unroll
        for (int n = 0; n < 5; n++)
#pragma unroll
            for (int x = 0; x < 4; x++) acc[m][n][x] = 0.f;

    // ---- prologue: B(0)+colc(0) cp.async into buf 0; adj(0) -> registers
    {
#pragma unroll
        for (int it = 0; it < 3; it++) {
            int l = t + 256 * it;
            if (l < 640) {
                int n = l >> 3, kc = l & 7;
                cp_async16(sbase + SM_B + (uint32_t)(n * (BSTR * 2) + kc * 16),
                           &g_Wht[(size_t)n * NN + jstart + kc * 8]);
            }
        }
        if (t < 64)
            cp_async16(sbase + SM_COLC + (uint32_t)t * 16, &g_colc[jstart + t]);
        cp_commit();
    }

    int2 av[16];
#pragma unroll
    for (int r = 0; r < 16; r++)
        av[r] = __ldcs((const int2*)(aptr + (size_t)r * NN + jstart));

    for (int tt = 0; tt < NTILES; tt++) {
        int buf = tt & 1;
        int j0 = jstart + tt * BK;

        // 1. all warps done with MMA(tt-1) (reads B[buf^1]) before refill
        __syncthreads();

        // 2. issue B(tt+1)/colc(tt+1) into buf^1
        if (tt + 1 < NTILES) {
            int jn = j0 + BK;
            uint32_t bd = sbase + SM_B + (uint32_t)(buf ^ 1) * (NB * BSTR * 2);
            uint32_t cd = sbase + SM_COLC + (uint32_t)(buf ^ 1) * 1024;
#pragma unroll
            for (int it = 0; it < 3; it++) {
                int l = t + 256 * it;
                if (l < 640) {
                    int n = l >> 3, kc = l & 7;
                    cp_async16(bd + (uint32_t)(n * (BSTR * 2) + kc * 16),
                               &g_Wht[(size_t)n * NN + jn + kc * 8]);
                }
            }
            if (t < 64) cp_async16(cd + (uint32_t)t * 16, &g_colc[jn + t]);
            cp_commit();
            cp_wait1();   // B(tt)/colc(tt) complete; tt+1 in flight
        } else {
            cp_wait0();
        }

        // 3. visibility of B(tt)/colc(tt)
        __syncthreads();

        // 4. w-gen: registers(adj) + smem consts -> fp16 A[128][64]
        {
            const float4* cl = (const float4*)(smem + SM_COLC + buf * 1024);
            float4 cc0 = cl[2 * lane];
            float4 cc1 = cl[2 * lane + 1];
            const float4* rw = (const float4*)(smem + SM_ROWC) + wrow0;
            __half2* adst = (__half2*)(smem + SM_A) + lane;
#pragma unroll
            for (int r = 0; r < 16; r++) {
                float4 rc = rw[r];                 // LDS broadcast
                int2 a2 = av[r];
                float w0 = ((rc.x + cc0.x) > 0.f) ? rc.y * cc0.y : rc.z * cc0.z;
                float w1 = ((rc.x + cc1.x) > 0.f) ? rc.y * cc1.y : rc.z * cc1.z;
                w0 = a2.x ? w0 : 0.f;
                w1 = a2.y ? w1 : 0.f;
                adst[(wrow0 + r) * (ASTR / 2)] = __floats2half2_rn(w0, w1);
            }
        }

        // 5. stream adj(tt+1) into registers (flies over sync + MMA)
        if (tt + 1 < NTILES) {
            int jn = j0 + BK;
#pragma unroll
            for (int r = 0; r < 16; r++)
                av[r] = __ldcs((const int2*)(aptr + (size_t)r * NN + jn));
        }

        // 6. A visible
        __syncthreads();

        // 7. MMA: 4 k-steps x (2 m-tiles x 5 n-tiles), ldmatrix fragments
        uint32_t b_base = sbase + SM_B + (uint32_t)buf * (NB * BSTR * 2);
#pragma unroll
        for (int kt = 0; kt < 4; kt++) {
            uint32_t koff = (uint32_t)kt * 32;    // 16 halves
            uint32_t a0[4], a1[4], bb[10];
            ldsm_x4(a0[0], a0[1], a0[2], a0[3], a_ad0 + koff);
            ldsm_x4(a1[0], a1[1], a1[2], a1[3], a_ad1 + koff);
            ldsm_x4(bb[0], bb[1], bb[2], bb[3], b_base + b_off_p + koff);
            ldsm_x4(bb[4], bb[5], bb[6], bb[7],
                    b_base + b_off_p + 16 * BSTR * 2 + koff);
            ldsm_x2(bb[8], bb[9], b_base + b_off_2 + koff);
#pragma unroll
            for (int nt = 0; nt < 5; nt++) {
                uint32_t b0 = bb[2 * nt], b1 = bb[2 * nt + 1];
                asm volatile(
                    "mma.sync.aligned.m16n8k16.row.col.f32.f16.f16.f32 "
                    "{%0,%1,%2,%3}, {%4,%5,%6,%7}, {%8,%9}, {%0,%1,%2,%3};\n"
                    : "+f"(acc[0][nt][0]), "+f"(acc[0][nt][1]),
                      "+f"(acc[0][nt][2]), "+f"(acc[0][nt][3])
                    : "r"(a0[0]), "r"(a0[1]), "r"(a0[2]), "r"(a0[3]),
                      "r"(b0), "r"(b1));
                asm volatile(
                    "mma.sync.aligned.m16n8k16.row.col.f32.f16.f16.f32 "
                    "{%0,%1,%2,%3}, {%4,%5,%6,%7}, {%8,%9}, {%0,%1,%2,%3};\n"
                    : "+f"(acc[1][nt][0]), "+f"(acc[1][nt][1]),
                      "+f"(acc[1][nt][2]), "+f"(acc[1][nt][3])
                    : "r"(a1[0]), "r"(a1[1]), "r"(a1[2]), "r"(a1[3]),
                      "r"(b0), "r"(b1));
            }
        }
    }

    // ---- write partials: nums (cols 0..63) + den (logical col 64)
    float* pp = &g_part[((size_t)split * NN + i0) * PART_STRIDE];
#pragma unroll
    for (int m = 0; m < 2; m++) {
        int r0 = mb + m * 16 + g, r1 = r0 + 8;
#pragma unroll
        for (int nt = 0; nt < 5; nt++) {
            int nb2 = nb + nt * 8 + 2 * tig;
            if (nb2 < 64) {
                pp[(size_t)r0 * PART_STRIDE + nb2] = acc[m][nt][0];
                pp[(size_t)r1 * PART_STRIDE + nb2] = acc[m][nt][2];
            }
            if (nb2 + 1 < 64) {
                pp[(size_t)r0 * PART_STRIDE + nb2 + 1] = acc[m][nt][1];
                pp[(size_t)r1 * PART_STRIDE + nb2 + 1] = acc[m][nt][3];
            }
        }
        if (nb == 40 && tig == 0) {    // col 64 = 40 + 3*8 + 0
            pp[(size_t)r0 * PART_STRIDE + 64] = acc[m][3][0];
            pp[(size_t)r1 * PART_STRIDE + 64] = acc[m][3][2];
        }
    }
}

// ---------------------------------------------------------------------------
// Kernel 5: reduce partials across splits + elu (float4 per thread).
// ---------------------------------------------------------------------------
__global__ __launch_bounds__(256) void k_reduce(float* __restrict__ out)
{
    int idx = blockIdx.x * 256 + threadIdx.x;   // 0 .. NN*16
    int i = idx >> 4;
    int c4 = (idx & 15) * 4;

    float4 num = make_float4(0.f, 0.f, 0.f, 0.f);
    float den = 0.f;
#pragma unroll
    for (int s = 0; s < NSPLIT; s++) {
        const float* pp = &g_part[((size_t)s * NN + i) * PART_STRIDE];
        float4 v = *(const float4*)(pp + c4);
        num.x += v.x; num.y += v.y; num.z += v.z; num.w += v.w;
        den += pp[64];
    }
    float4 r;
    r.x = elu_f(num.x / den);
    r.y = elu_f(num.y / den);
    r.z = elu_f(num.z / den);
    r.w = elu_f(num.w / den);
    *(float4*)&out[(size_t)i * FOUT + c4] = r;
}

// ---------------------------------------------------------------------------
extern "C" void kernel_launch(void* const* d_in, const int* in_sizes, int n_in,
                              void* d_out, int out_size)
{
    const float* h   = (const float*)d_in[0];
    const int*   adj = (const int*)d_in[1];
    const float* W   = (const float*)d_in[2];
    const float* a   = (const float*)d_in[3];
    float* out = (float*)d_out;

    cudaFuncSetAttribute(k_gat, cudaFuncAttributeMaxDynamicSharedMemorySize,
                         SMEM_TOTAL);

    k_gemm_wh<<<NN / 16, 256>>>(h, W);
    k_fvec<<<NN / 256, 256>>>(a);
    k_consts<<<NN / 256, 256>>>();
    k_gat<<<(NN / BM) * NSPLIT, 256, SMEM_TOTAL>>>(adj);
    k_reduce<<<NN * 16 / 256, 256>>>(out);
}